// round 2
// baseline (speedup 1.0000x reference)
#include <cuda_runtime.h>
#include <math.h>

#define B_ 128
#define T_ 512
#define F_ 256
#define H_ 512
#define NBLK 128
#define NTHR 256

// Scratch (device globals: allocation-free per harness rules)
__device__ float g_xproj[(size_t)T_ * 4 * B_ * H_];   // [t][gate][b][h], 512 MB
__device__ float g_hT[H_ * B_];                        // transposed hidden [h][b]
__device__ float g_c[B_ * H_];                         // [b][h]
__device__ float g_n[B_ * H_];                         // [b][h]
__device__ float g_hr[4 * B_ * H_];                    // gate preacts [g][b][h]
__device__ unsigned g_barrier;

// ---------------------------------------------------------------------------
__global__ void init_kernel() {
    int i = blockIdx.x * blockDim.x + threadIdx.x;
    if (i < B_ * H_) {
        g_hT[i] = 0.f;
        g_c[i] = 0.f;
        g_n[i] = 0.f;
    }
    if (i == 0) g_barrier = 0u;
}

// ---------------------------------------------------------------------------
// Input projections: y[t][g][b][h] = sum_f x[b][t][f] * Wg[f][h] + bg[h]
// x is a [B*T, F] row-major matrix (row m = b*T + t).
// ---------------------------------------------------------------------------
__global__ __launch_bounds__(256) void proj_kernel(
    const float* __restrict__ x,
    const float* __restrict__ W0, const float* __restrict__ b0,
    const float* __restrict__ W1, const float* __restrict__ b1,
    const float* __restrict__ W2, const float* __restrict__ b2,
    const float* __restrict__ W3, const float* __restrict__ b3)
{
    const int g  = blockIdx.x >> 3;          // 4 gates
    const int n0 = (blockIdx.x & 7) * 64;    // h tile
    const int m0 = blockIdx.y * 64;          // (b,t) row tile

    const float* __restrict__ W    = (g == 0) ? W0 : (g == 1) ? W1 : (g == 2) ? W2 : W3;
    const float* __restrict__ bias = (g == 0) ? b0 : (g == 1) ? b1 : (g == 2) ? b2 : b3;

    __shared__ float As[16][64];   // [k][m]
    __shared__ float Bs[16][64];   // [k][n]

    const int tid = threadIdx.x;
    const int tx  = tid & 15;
    const int ty  = tid >> 4;

    const int lm  = tid >> 2;
    const int lk4 = (tid & 3) * 4;
    const int wk  = tid >> 4;
    const int wn4 = (tid & 15) * 4;

    float acc[4][4] = {};

    for (int k0 = 0; k0 < F_; k0 += 16) {
        float4 xa = *(const float4*)&x[(size_t)(m0 + lm) * F_ + k0 + lk4];
        As[lk4 + 0][lm] = xa.x;
        As[lk4 + 1][lm] = xa.y;
        As[lk4 + 2][lm] = xa.z;
        As[lk4 + 3][lm] = xa.w;
        *(float4*)&Bs[wk][wn4] =
            *(const float4*)&W[(size_t)(k0 + wk) * H_ + n0 + wn4];
        __syncthreads();

#pragma unroll
        for (int k = 0; k < 16; k++) {
            float4 a = *(const float4*)&As[k][ty * 4];
            float4 b = *(const float4*)&Bs[k][tx * 4];
            float av[4] = {a.x, a.y, a.z, a.w};
            float bv[4] = {b.x, b.y, b.z, b.w};
#pragma unroll
            for (int i = 0; i < 4; i++)
#pragma unroll
                for (int j = 0; j < 4; j++)
                    acc[i][j] += av[i] * bv[j];
        }
        __syncthreads();
    }

#pragma unroll
    for (int i = 0; i < 4; i++) {
        int m = m0 + ty * 4 + i;
        int b = m >> 9;       // m / T_
        int t = m & 511;      // m % T_
        float* out = &g_xproj[(((size_t)t * 4 + g) * B_ + b) * H_ + n0 + tx * 4];
#pragma unroll
        for (int j = 0; j < 4; j++)
            out[j] = acc[i][j] + bias[n0 + tx * 4 + j];
    }
}

// ---------------------------------------------------------------------------
// Grid-wide barrier: release-fence, arrive, spin, block barrier.
// Safe because all NBLK blocks are co-resident (128 <= 148 SMs, 1 block fits).
// ---------------------------------------------------------------------------
__device__ __forceinline__ void gsync(unsigned target) {
    __threadfence();          // release: drain this thread's global stores
    __syncthreads();
    if (threadIdx.x == 0) {
        atomicAdd(&g_barrier, 1u);
        while (*((volatile unsigned*)&g_barrier) < target) { }
    }
    __syncthreads();
}

// ---------------------------------------------------------------------------
// Persistent recurrent kernel. 128 blocks x 256 threads.
// Block bid: gate g = bid>>5, h-slice n0 = (bid&31)*16.
//   Phase A: hr[g][b][n0..n0+16) = h @ R_g[:, n0:n0+16)   (R slice in smem)
//   Phase B: block bid owns batch row b = bid: pointwise sLSTM update.
// Cross-SM data (hT, hr) is read via __ldcg (L2) since L1 is not coherent.
// ---------------------------------------------------------------------------
__global__ __launch_bounds__(NTHR) void recurrent_kernel(
    const float* __restrict__ Rf, const float* __restrict__ Ri,
    const float* __restrict__ Ro, const float* __restrict__ Rz)
{
    const int bid = blockIdx.x;
    const int tid = threadIdx.x;
    const int g   = bid >> 5;             // 0..3
    const int n0  = (bid & 31) << 4;      // 0,16,...,496

    const float* __restrict__ R = (g == 0) ? Rf : (g == 1) ? Ri : (g == 2) ? Ro : Rz;

    __shared__ float Rs[H_ * 16];         // [k][16] slice, 32 KB

    for (int idx = tid; idx < H_ * 16; idx += NTHR) {
        int k = idx >> 4;
        int n = idx & 15;
        Rs[idx] = R[(size_t)k * H_ + n0 + n];
    }
    __syncthreads();

    const int ng = tid & 7;               // h pair: n0 + ng*2
    const int bg = tid >> 3;              // batch group: bg*4 .. bg*4+3
    const int pb = bid;                   // phase-B batch row

    unsigned epoch = 0;

    for (int t = 0; t < T_; t++) {
        // ---------------- Phase A: GEMM slice ----------------
        float acc[4][2] = {};
        const float* __restrict__ hT = g_hT;
        const float* __restrict__ rs = Rs + (ng << 1);

#pragma unroll 8
        for (int k = 0; k < H_; k++) {
            float4 a = __ldcg((const float4*)(hT + (size_t)k * B_ + (bg << 2)));
            float2 r = *(const float2*)(rs + k * 16);
            acc[0][0] += a.x * r.x;  acc[0][1] += a.x * r.y;
            acc[1][0] += a.y * r.x;  acc[1][1] += a.y * r.y;
            acc[2][0] += a.z * r.x;  acc[2][1] += a.z * r.y;
            acc[3][0] += a.w * r.x;  acc[3][1] += a.w * r.y;
        }

#pragma unroll
        for (int i = 0; i < 4; i++) {
            float2 v = make_float2(acc[i][0], acc[i][1]);
            *(float2*)&g_hr[((size_t)g * B_ + (bg << 2) + i) * H_ + n0 + (ng << 1)] = v;
        }

        epoch++;
        gsync(epoch * NBLK);

        // ---------------- Phase B: pointwise sLSTM update ----------------
        const float* __restrict__ xp = g_xproj + (size_t)t * 4 * B_ * H_;
#pragma unroll
        for (int e = 0; e < 2; e++) {
            int h = tid + e * NTHR;
            size_t bh = (size_t)pb * H_ + h;

            float ft = __ldcg(&g_hr[((size_t)0 * B_ + pb) * H_ + h]) + xp[((size_t)0 * B_ + pb) * H_ + h];
            float it = __ldcg(&g_hr[((size_t)1 * B_ + pb) * H_ + h]) + xp[((size_t)1 * B_ + pb) * H_ + h];
            float ot = __ldcg(&g_hr[((size_t)2 * B_ + pb) * H_ + h]) + xp[((size_t)2 * B_ + pb) * H_ + h];
            float zt = __ldcg(&g_hr[((size_t)3 * B_ + pb) * H_ + h]) + xp[((size_t)3 * B_ + pb) * H_ + h];

            float o  = 1.f / (1.f + expf(-ot));
            float z  = tanhf(zt);
            float fh = expf(fminf(ft, 10.f));
            float ih = expf(fminf(it, 10.f));
            float denom = fh + ih + 1e-8f;
            float f  = fh / denom;
            float ii = ih / denom;

            float c = f * g_c[bh] + ii * z;   // c,n private to this block
            float n = f * g_n[bh] + ii;
            g_c[bh] = c;
            g_n[bh] = n;
            g_hT[(size_t)h * B_ + pb] = o * (c / (n + 1e-8f));
        }

        epoch++;
        gsync(epoch * NBLK);
    }
}

// ---------------------------------------------------------------------------
// Head: out[b] = tanh(sum_k hT[k][b] * fc_w[k] + fc_b)
// ---------------------------------------------------------------------------
__global__ __launch_bounds__(128) void head_kernel(
    const float* __restrict__ fcw, const float* __restrict__ fcb,
    float* __restrict__ out)
{
    int b = blockIdx.x;
    float s = 0.f;
    for (int k = threadIdx.x; k < H_; k += 128)
        s += g_hT[(size_t)k * B_ + b] * fcw[k];

    __shared__ float red[4];
#pragma unroll
    for (int off = 16; off; off >>= 1)
        s += __shfl_down_sync(0xffffffff, s, off);
    if ((threadIdx.x & 31) == 0) red[threadIdx.x >> 5] = s;
    __syncthreads();
    if (threadIdx.x == 0) {
        float tot = red[0] + red[1] + red[2] + red[3];
        out[b] = tanhf(tot + fcb[0]);
    }
}

// ---------------------------------------------------------------------------
extern "C" void kernel_launch(void* const* d_in, const int* in_sizes, int n_in,
                              void* d_out, int out_size)
{
    const float* x   = (const float*)d_in[0];
    const float* Wf  = (const float*)d_in[1];
    const float* bf  = (const float*)d_in[2];
    const float* Wi  = (const float*)d_in[3];
    const float* bi  = (const float*)d_in[4];
    const float* Wo  = (const float*)d_in[5];
    const float* bo  = (const float*)d_in[6];
    const float* Wz  = (const float*)d_in[7];
    const float* bz  = (const float*)d_in[8];
    const float* Rf  = (const float*)d_in[9];
    const float* Ri  = (const float*)d_in[10];
    const float* Ro  = (const float*)d_in[11];
    const float* Rz  = (const float*)d_in[12];
    const float* fcw = (const float*)d_in[13];
    const float* fcb = (const float*)d_in[14];
    float* out = (float*)d_out;

    init_kernel<<<(B_ * H_ + 255) / 256, 256>>>();

    dim3 gA(32, (B_ * T_) / 64);   // (4 gates * 8 n-tiles, 1024 m-tiles)
    proj_kernel<<<gA, 256>>>(x, Wf, bf, Wi, bi, Wo, bo, Wz, bz);

    recurrent_kernel<<<NBLK, NTHR>>>(Rf, Ri, Ro, Rz);

    head_kernel<<<B_, 128>>>(fcw, fcb, out);
}

// round 3
// speedup vs baseline: 3.2009x; 3.2009x over previous
#include <cuda_runtime.h>
#include <math.h>

#define B_ 128
#define T_ 512
#define F_ 256
#define H_ 512
#define NBLK 128
#define NTHR 256
#define KT 64
#define NTILES (H_ / KT)

// Scratch (device globals: allocation-free per harness rules)
__device__ float g_xproj[(size_t)T_ * H_ * 4 * B_];   // [t][h][g][b], 512 MB
__device__ float g_hT[2][H_ * B_];                     // [parity][h][b]
__device__ volatile unsigned g_arrive;
__device__ volatile unsigned g_release;

// ---------------------------------------------------------------------------
__global__ void init_kernel() {
    int i = blockIdx.x * blockDim.x + threadIdx.x;
    if (i < H_ * B_) g_hT[0][i] = 0.f;
    if (i == 0) { g_arrive = 0u; g_release = 0u; }
}

// ---------------------------------------------------------------------------
// Input projections: xproj[t][h][g][b] = sum_f x[b][t][f] * Wg[f][h] + bg[h]
// M-tile = 64 batches at ONE t (so stores are contiguous in b -> float4 STG).
// ---------------------------------------------------------------------------
__global__ __launch_bounds__(256) void proj_kernel(
    const float* __restrict__ x,
    const float* __restrict__ W0, const float* __restrict__ b0v,
    const float* __restrict__ W1, const float* __restrict__ b1v,
    const float* __restrict__ W2, const float* __restrict__ b2v,
    const float* __restrict__ W3, const float* __restrict__ b3v)
{
    const int g  = blockIdx.x >> 3;          // 4 gates
    const int n0 = (blockIdx.x & 7) * 64;    // h tile
    const int t  = blockIdx.y >> 1;          // time index
    const int b0 = (blockIdx.y & 1) * 64;    // batch tile

    const float* __restrict__ W    = (g == 0) ? W0 : (g == 1) ? W1 : (g == 2) ? W2 : W3;
    const float* __restrict__ bias = (g == 0) ? b0v : (g == 1) ? b1v : (g == 2) ? b2v : b3v;

    __shared__ float As[16][64];   // [k][b]
    __shared__ float Bs[16][64];   // [k][h]

    const int tid = threadIdx.x;
    const int tx  = tid & 15;      // h: tx*4
    const int ty  = tid >> 4;      // b: ty*4

    const int lm  = tid >> 2;         // 0..63 (batch row)
    const int lk4 = (tid & 3) * 4;    // 0,4,8,12
    const int wk  = tid >> 4;         // 0..15
    const int wn4 = (tid & 15) * 4;   // 0..60

    float acc[4][4] = {};   // [i: b][j: h]

    for (int k0 = 0; k0 < F_; k0 += 16) {
        float4 xa = *(const float4*)&x[((size_t)(b0 + lm) * T_ + t) * F_ + k0 + lk4];
        As[lk4 + 0][lm] = xa.x;
        As[lk4 + 1][lm] = xa.y;
        As[lk4 + 2][lm] = xa.z;
        As[lk4 + 3][lm] = xa.w;
        *(float4*)&Bs[wk][wn4] =
            *(const float4*)&W[(size_t)(k0 + wk) * H_ + n0 + wn4];
        __syncthreads();

#pragma unroll
        for (int k = 0; k < 16; k++) {
            float4 a = *(const float4*)&As[k][ty * 4];
            float4 b = *(const float4*)&Bs[k][tx * 4];
            float av[4] = {a.x, a.y, a.z, a.w};
            float bv[4] = {b.x, b.y, b.z, b.w};
#pragma unroll
            for (int i = 0; i < 4; i++)
#pragma unroll
                for (int j = 0; j < 4; j++)
                    acc[i][j] += av[i] * bv[j];
        }
        __syncthreads();
    }

    // Store: [t][h][g][b], float4 over 4 consecutive b
#pragma unroll
    for (int j = 0; j < 4; j++) {
        int h = n0 + tx * 4 + j;
        float bb = bias[h];
        float4 v = make_float4(acc[0][j] + bb, acc[1][j] + bb,
                               acc[2][j] + bb, acc[3][j] + bb);
        *(float4*)&g_xproj[(((size_t)t * H_ + h) * 4 + g) * B_ + b0 + ty * 4] = v;
    }
}

// ---------------------------------------------------------------------------
// Grid barrier: single counter arrive, separate release word (read-only poll).
// ---------------------------------------------------------------------------
__device__ __forceinline__ void gsync(unsigned epoch) {
    __syncthreads();
    if (threadIdx.x == 0) {
        __threadfence();
        unsigned a = atomicAdd((unsigned*)&g_arrive, 1u) + 1u;
        if (a == epoch * NBLK) {
            g_release = epoch;
            __threadfence();
        } else {
            while (g_release < epoch) { }
            __threadfence();
        }
    }
    __syncthreads();
}

// ---------------------------------------------------------------------------
// Persistent recurrent kernel: 128 blocks x 256 threads, 1 block/SM.
// Block owns 4 h-columns (n0=bid*4), ALL 4 gates, ALL 128 batches:
//   GEMM:  pre[g][col][b] = sum_k h[k][b] * Rg[k][n0+col]  (R slice in smem,
//          h k-tiles staged smem<-L2 via cp.async.cg, double buffered)
//   UPDATE: block-local sLSTM pointwise; c,n live in registers; writes h cols.
// One grid sync per step (h double-buffered by parity).
// ---------------------------------------------------------------------------
__global__ __launch_bounds__(NTHR) void recurrent_kernel(
    const float* __restrict__ Rf, const float* __restrict__ Ri,
    const float* __restrict__ Ro, const float* __restrict__ Rz)
{
    extern __shared__ float smem[];
    float* Rs  = smem;                           // [512][16] : [k][g*4+col]
    float* Hs  = smem + H_ * 16;                 // [2][KT][128]
    float* pre = smem + H_ * 16 + 2 * KT * B_;   // [16][132] : [g*4+col][b]

    const int bid = blockIdx.x;
    const int tid = threadIdx.x;
    const int n0  = bid * 4;

    // Stage R slices once: Rs[k][g*4+c] = Rg[k][n0+c]
    {
        const float* Rm[4] = {Rf, Ri, Ro, Rz};
        for (int idx = tid; idx < H_ * 16; idx += NTHR) {
            int k = idx >> 4;
            int g = (idx >> 2) & 3;
            int c = idx & 3;
            Rs[idx] = Rm[g][(size_t)k * H_ + n0 + c];
        }
    }
    __syncthreads();

    // GEMM thread mapping
    const int p  = tid & 1;          // col pair: cols p*2, p*2+1
    const int g  = (tid >> 1) & 3;   // gate
    const int bq = tid >> 3;         // batch quad: b = bq*4..bq*4+3
    const float* rs_t = Rs + g * 4 + p * 2;

    // Update thread mapping: 2 elements (col, b) and (col, b+1)
    const int ue   = tid * 2;
    const int ucol = ue >> 7;        // 0..3
    const int ub   = ue & 127;       // even

    float c_reg[2] = {0.f, 0.f};
    float n_reg[2] = {0.f, 0.f};

    unsigned epoch = 0;

    for (int t = 0; t < T_; t++) {
        const int par = t & 1;
        const float* __restrict__ hsrc = g_hT[par];

        // ---- prefetch k-tile 0 ----
        {
            const float4* src = (const float4*)hsrc;
#pragma unroll
            for (int u = 0; u < 8; u++) {
                int fidx = u * NTHR + tid;
                unsigned dst = (unsigned)__cvta_generic_to_shared(Hs + fidx * 4);
                asm volatile("cp.async.cg.shared.global [%0], [%1], 16;\n"
                             :: "r"(dst), "l"(src + fidx));
            }
            asm volatile("cp.async.commit_group;\n");
        }

        float acc[4][2] = {};
        int buf = 0;

        for (int kt = 0; kt < NTILES; kt++) {
            asm volatile("cp.async.wait_group 0;\n");
            __syncthreads();

            if (kt + 1 < NTILES) {
                const float4* src = (const float4*)(hsrc + (kt + 1) * KT * B_);
                float* dstb = Hs + (buf ^ 1) * KT * B_;
#pragma unroll
                for (int u = 0; u < 8; u++) {
                    int fidx = u * NTHR + tid;
                    unsigned dst = (unsigned)__cvta_generic_to_shared(dstb + fidx * 4);
                    asm volatile("cp.async.cg.shared.global [%0], [%1], 16;\n"
                                 :: "r"(dst), "l"(src + fidx));
                }
                asm volatile("cp.async.commit_group;\n");
            }

            const float* hs_t = Hs + buf * KT * B_ + bq * 4;
            const float* rk   = rs_t + kt * KT * 16;
#pragma unroll 8
            for (int k = 0; k < KT; k++) {
                float4 a = *(const float4*)(hs_t + k * B_);
                float2 r = *(const float2*)(rk + k * 16);
                acc[0][0] += a.x * r.x;  acc[0][1] += a.x * r.y;
                acc[1][0] += a.y * r.x;  acc[1][1] += a.y * r.y;
                acc[2][0] += a.z * r.x;  acc[2][1] += a.z * r.y;
                acc[3][0] += a.w * r.x;  acc[3][1] += a.w * r.y;
            }
            buf ^= 1;
        }

        // ---- write preacts to smem ----
#pragma unroll
        for (int j = 0; j < 2; j++)
#pragma unroll
            for (int i = 0; i < 4; i++)
                pre[(g * 4 + p * 2 + j) * 132 + bq * 4 + i] = acc[i][j];
        __syncthreads();

        // ---- pointwise sLSTM update (block-local) ----
        {
            const float* __restrict__ xp =
                g_xproj + ((size_t)t * H_ + n0) * 4 * B_;   // [h_loc][g][b]

            float2 hrf = *(const float2*)&pre[(0 * 4 + ucol) * 132 + ub];
            float2 hri = *(const float2*)&pre[(1 * 4 + ucol) * 132 + ub];
            float2 hro = *(const float2*)&pre[(2 * 4 + ucol) * 132 + ub];
            float2 hrz = *(const float2*)&pre[(3 * 4 + ucol) * 132 + ub];
            float2 xf = *(const float2*)&xp[((size_t)ucol * 4 + 0) * B_ + ub];
            float2 xi = *(const float2*)&xp[((size_t)ucol * 4 + 1) * B_ + ub];
            float2 xo = *(const float2*)&xp[((size_t)ucol * 4 + 2) * B_ + ub];
            float2 xz = *(const float2*)&xp[((size_t)ucol * 4 + 3) * B_ + ub];

            float ftv[2] = {hrf.x + xf.x, hrf.y + xf.y};
            float itv[2] = {hri.x + xi.x, hri.y + xi.y};
            float otv[2] = {hro.x + xo.x, hro.y + xo.y};
            float ztv[2] = {hrz.x + xz.x, hrz.y + xz.y};

            float hv[2];
#pragma unroll
            for (int e = 0; e < 2; e++) {
                float o  = 1.f / (1.f + __expf(-otv[e]));
                float z  = tanhf(ztv[e]);
                float fh = __expf(fminf(ftv[e], 10.f));
                float ih = __expf(fminf(itv[e], 10.f));
                float dn = fh + ih + 1e-8f;
                float f  = fh / dn;
                float ii = ih / dn;
                c_reg[e] = f * c_reg[e] + ii * z;
                n_reg[e] = f * n_reg[e] + ii;
                hv[e] = o * (c_reg[e] / (n_reg[e] + 1e-8f));
            }
            *(float2*)&g_hT[par ^ 1][(n0 + ucol) * B_ + ub] =
                make_float2(hv[0], hv[1]);
        }

        epoch++;
        gsync(epoch);
    }
}

// ---------------------------------------------------------------------------
// Head: out[b] = tanh(sum_k h[k][b] * fc_w[k] + fc_b). Final h in g_hT[0].
// ---------------------------------------------------------------------------
__global__ __launch_bounds__(128) void head_kernel(
    const float* __restrict__ fcw, const float* __restrict__ fcb,
    float* __restrict__ out)
{
    int b = blockIdx.x;
    float s = 0.f;
    for (int k = threadIdx.x; k < H_; k += 128)
        s += g_hT[0][(size_t)k * B_ + b] * fcw[k];

    __shared__ float red[4];
#pragma unroll
    for (int off = 16; off; off >>= 1)
        s += __shfl_down_sync(0xffffffff, s, off);
    if ((threadIdx.x & 31) == 0) red[threadIdx.x >> 5] = s;
    __syncthreads();
    if (threadIdx.x == 0) {
        float tot = red[0] + red[1] + red[2] + red[3];
        out[b] = tanhf(tot + fcb[0]);
    }
}

// ---------------------------------------------------------------------------
extern "C" void kernel_launch(void* const* d_in, const int* in_sizes, int n_in,
                              void* d_out, int out_size)
{
    const float* x   = (const float*)d_in[0];
    const float* Wf  = (const float*)d_in[1];
    const float* bf  = (const float*)d_in[2];
    const float* Wi  = (const float*)d_in[3];
    const float* bi  = (const float*)d_in[4];
    const float* Wo  = (const float*)d_in[5];
    const float* bo  = (const float*)d_in[6];
    const float* Wz  = (const float*)d_in[7];
    const float* bz  = (const float*)d_in[8];
    const float* Rf  = (const float*)d_in[9];
    const float* Ri  = (const float*)d_in[10];
    const float* Ro  = (const float*)d_in[11];
    const float* Rz  = (const float*)d_in[12];
    const float* fcw = (const float*)d_in[13];
    const float* fcb = (const float*)d_in[14];
    float* out = (float*)d_out;

    const int smem_bytes = (H_ * 16 + 2 * KT * B_ + 16 * 132) * sizeof(float);
    cudaFuncSetAttribute(recurrent_kernel,
                         cudaFuncAttributeMaxDynamicSharedMemorySize, smem_bytes);

    init_kernel<<<(H_ * B_ + 255) / 256, 256>>>();

    dim3 gA(32, T_ * 2);   // (4 gates * 8 h-tiles, 512 t * 2 b-tiles)
    proj_kernel<<<gA, 256>>>(x, Wf, bf, Wi, bi, Wo, bo, Wz, bz);

    recurrent_kernel<<<NBLK, NTHR, smem_bytes>>>(Rf, Ri, Ro, Rz);

    head_kernel<<<B_, 128>>>(fcw, fcb, out);
}